// round 5
// baseline (speedup 1.0000x reference)
#include <cuda_runtime.h>
#include <math.h>
#include <cstdint>

// Problem constants
#define BATCH   2048
#define LAT     256
#define HID     1024
#define OUTD    512
#define TSTEPS  100
#define NSUB    10
#define NCTA    128

enum { MODE_ELU = 0, MODE_EULER = 1, MODE_PLAIN = 2 };

// ---------------------------------------------------------------------------
// Device scratch (no cudaMalloc allowed)
// ---------------------------------------------------------------------------
__device__ __align__(256) float g_zs[(size_t)TSTEPS * BATCH * LAT];
__device__ __align__(256) float g_h1[(size_t)BATCH * HID];
__device__ __align__(256) float g_h2[(size_t)BATCH * HID];
__device__ __align__(256) float g_za[(size_t)BATCH * LAT];
__device__ __align__(256) float g_zb[(size_t)BATCH * LAT];
__device__ __align__(256) float g_Md[(size_t)OUTD * LAT];
__device__ __align__(256) float g_cd[OUTD];

// grid-barrier state (returns to 0 each launch: even #barriers, count resets)
__device__ unsigned g_cnt;
__device__ unsigned g_sense;

// Dynamic smem: double-buffered permuted tiles, row stride 36 floats.
// Per buffer (BM=BN=128): 4 tiles x 128 x 36 floats = 73728 B; x2 = 147456 B.
#define SMEM_BYTES 147456

// ---------------------------------------------------------------------------
// Helpers
// ---------------------------------------------------------------------------
__device__ __forceinline__ float tf32_rna(float x) {
    uint32_t u;
    asm("cvt.rna.tf32.f32 %0, %1;" : "=r"(u) : "f"(x));
    return __uint_as_float(u);
}

// D += A*B (m16n8k8, tf32 inputs as bit patterns, fp32 accumulate)
__device__ __forceinline__ void mma8(float (&d)[4],
                                     float a0, float a1, float a2, float a3,
                                     float b0, float b1) {
    asm volatile(
        "mma.sync.aligned.m16n8k8.row.col.f32.tf32.tf32.f32 "
        "{%0,%1,%2,%3}, {%4,%5,%6,%7}, {%8,%9}, {%0,%1,%2,%3};"
        : "+f"(d[0]), "+f"(d[1]), "+f"(d[2]), "+f"(d[3])
        : "r"(__float_as_uint(a0)), "r"(__float_as_uint(a1)),
          "r"(__float_as_uint(a2)), "r"(__float_as_uint(a3)),
          "r"(__float_as_uint(b0)), "r"(__float_as_uint(b1)));
}

// ---------------------------------------------------------------------------
// Grid barrier: release/acquire at gpu scope (no MEMBAR.GPU, no L1D flush).
// ---------------------------------------------------------------------------
__device__ __forceinline__ void grid_sync(unsigned* s_sense) {
    __syncthreads();
    if (threadIdx.x == 0) {
        unsigned my = *s_sense ^ 1u;
        *s_sense = my;
        unsigned old;
        asm volatile("atom.release.gpu.global.add.u32 %0, [%1], %2;"
                     : "=r"(old) : "l"(&g_cnt), "r"(1u) : "memory");
        if (old == NCTA - 1u) {
            asm volatile("st.relaxed.gpu.global.u32 [%0], %1;" :: "l"(&g_cnt), "r"(0u) : "memory");
            asm volatile("st.release.gpu.global.u32 [%0], %1;" :: "l"(&g_sense), "r"(my) : "memory");
        } else {
            unsigned cur;
            do {
                asm volatile("ld.acquire.gpu.global.u32 %0, [%1];"
                             : "=r"(cur) : "l"(&g_sense) : "memory");
            } while (cur != my);
        }
    }
    __syncthreads();
}

// ---------------------------------------------------------------------------
// One BM x BN output tile:  C[m,n] = epilogue( sum_k A[m,k]*W[n,k] + bias[n] )
// 3-term tf32 split (AhBh + AhBl + AlBh), fp32 register accumulators.
// 256 threads = 8 warps (4x2). Double-buffered smem, permuted layout:
//   element (row,k) of a 32-k chunk at float offset row*36 + (k&3)*8 + (k>>2)
// so fragment loads are float4 (4-phase optimal with stride 36).
// ---------------------------------------------------------------------------
template <int BM, int BN, int MODE>
__device__ __forceinline__ void tile_mma(
    const float* __restrict__ A, const float* __restrict__ W,
    const float* __restrict__ bias, const float* __restrict__ Zp,
    float* __restrict__ C, int N, int K, float h,
    int mB, int nB, float* sm) {

    constexpr int WM  = BM / 4;        // warp tile M (4x2 warp grid)
    constexpr int WN  = BN / 2;        // warp tile N
    constexpr int MT  = WM / 16;       // mma tiles per warp (M)
    constexpr int NT  = WN / 8;        // mma tiles per warp (N)
    constexpr int APT = BM * 8 / 256;  // A float4 per thread per chunk
    constexpr int BPT = BN * 8 / 256;  // B float4 per thread per chunk
    constexpr int AT  = BM * 36;       // floats per A tile
    constexpr int BT  = BN * 36;       // floats per B tile
    constexpr int BUF = 2 * AT + 2 * BT;

    const int tid  = threadIdx.x;
    const int lane = tid & 31;
    const int warp = tid >> 5;
    const int wm   = warp >> 1;        // 0..3
    const int wn   = warp & 1;         // 0..1
    const int nTc  = K >> 5;

    float4 ra[APT], rb[BPT];
    float acc[MT][NT][4];
#pragma unroll
    for (int i = 0; i < MT; i++)
#pragma unroll
        for (int j = 0; j < NT; j++)
#pragma unroll
            for (int c = 0; c < 4; c++) acc[i][j][c] = 0.0f;

    auto ldg_chunk = [&](int t) {
#pragma unroll
        for (int i = 0; i < APT; i++) {
            int idx = tid + i * 256, row = idx >> 3, c4 = idx & 7;
            ra[i] = __ldcg((const float4*)(A + (size_t)(mB + row) * K + t * 32 + c4 * 4));
        }
#pragma unroll
        for (int i = 0; i < BPT; i++) {
            int idx = tid + i * 256, row = idx >> 3, c4 = idx & 7;
            rb[i] = __ldg((const float4*)(W + (size_t)(nB + row) * K + t * 32 + c4 * 4));
        }
    };

    // permuted scatter: k = 4*c4 + e  ->  offset row*36 + e*8 + c4
    auto sts_chunk = [&](int buf) {
        float* sAh = sm + buf * BUF;
        float* sAl = sAh + AT;
        float* sBh = sAl + AT;
        float* sBl = sBh + BT;
#pragma unroll
        for (int i = 0; i < APT; i++) {
            int idx = tid + i * 256, row = idx >> 3, c4 = idx & 7;
            const int p = row * 36 + c4;
            float4 v = ra[i];
            float hx = tf32_rna(v.x), hy = tf32_rna(v.y);
            float hz = tf32_rna(v.z), hw = tf32_rna(v.w);
            sAh[p] = hx; sAh[p + 8] = hy; sAh[p + 16] = hz; sAh[p + 24] = hw;
            sAl[p] = tf32_rna(v.x - hx); sAl[p + 8]  = tf32_rna(v.y - hy);
            sAl[p + 16] = tf32_rna(v.z - hz); sAl[p + 24] = tf32_rna(v.w - hw);
        }
#pragma unroll
        for (int i = 0; i < BPT; i++) {
            int idx = tid + i * 256, row = idx >> 3, c4 = idx & 7;
            const int p = row * 36 + c4;
            float4 v = rb[i];
            float hx = tf32_rna(v.x), hy = tf32_rna(v.y);
            float hz = tf32_rna(v.z), hw = tf32_rna(v.w);
            sBh[p] = hx; sBh[p + 8] = hy; sBh[p + 16] = hz; sBh[p + 24] = hw;
            sBl[p] = tf32_rna(v.x - hx); sBl[p + 8]  = tf32_rna(v.y - hy);
            sBl[p + 16] = tf32_rna(v.z - hz); sBl[p + 24] = tf32_rna(v.w - hw);
        }
    };

    const int rA = wm * WM + (lane >> 2);
    const int rB = wn * WN + (lane >> 2);
    const int cK = lane & 3;

    ldg_chunk(0);
    sts_chunk(0);
    __syncthreads();

    for (int t = 0; t < nTc; ++t) {
        if (t + 1 < nTc) ldg_chunk(t + 1);

        const float* sAh = sm + (t & 1) * BUF;
        const float* sAl = sAh + AT;
        const float* sBh = sAl + AT;
        const float* sBl = sBh + BT;

#pragma unroll
        for (int kk = 0; kk < 2; kk++) {            // kk covers k8 = 2kk, 2kk+1
            float4 fAh[MT][2], fAl[MT][2];
#pragma unroll
            for (int i = 0; i < MT; i++) {
                const int r0 = (rA + i * 16) * 36 + cK * 8 + kk * 4;
                const int r1 = r0 + 8 * 36;
                fAh[i][0] = *(const float4*)(sAh + r0);
                fAh[i][1] = *(const float4*)(sAh + r1);
                fAl[i][0] = *(const float4*)(sAl + r0);
                fAl[i][1] = *(const float4*)(sAl + r1);
            }
#pragma unroll
            for (int j = 0; j < NT; j++) {
                const int rn = (rB + j * 8) * 36 + cK * 8 + kk * 4;
                const float4 fbh = *(const float4*)(sBh + rn);
                const float4 fbl = *(const float4*)(sBl + rn);
                // s = 0 (k8 = 2kk): fragments in .x/.y ; s = 1: .z/.w
#pragma unroll
                for (int i = 0; i < MT; i++) {
                    mma8(acc[i][j], fAh[i][0].x, fAh[i][1].x, fAh[i][0].y, fAh[i][1].y, fbh.x, fbh.y);
                    mma8(acc[i][j], fAh[i][0].x, fAh[i][1].x, fAh[i][0].y, fAh[i][1].y, fbl.x, fbl.y);
                    mma8(acc[i][j], fAl[i][0].x, fAl[i][1].x, fAl[i][0].y, fAl[i][1].y, fbh.x, fbh.y);
                }
#pragma unroll
                for (int i = 0; i < MT; i++) {
                    mma8(acc[i][j], fAh[i][0].z, fAh[i][1].z, fAh[i][0].w, fAh[i][1].w, fbh.z, fbh.w);
                    mma8(acc[i][j], fAh[i][0].z, fAh[i][1].z, fAh[i][0].w, fAh[i][1].w, fbl.z, fbl.w);
                    mma8(acc[i][j], fAl[i][0].z, fAl[i][1].z, fAl[i][0].w, fAl[i][1].w, fbh.z, fbh.w);
                }
            }
        }

        if (t + 1 < nTc) {
            sts_chunk((t + 1) & 1);
            __syncthreads();
        }
    }

    // ---- epilogue: bias + mode, float2 stores straight from accumulators ----
#pragma unroll
    for (int i = 0; i < MT; i++) {
        const int gm0 = mB + wm * WM + i * 16 + (lane >> 2);
#pragma unroll
        for (int j = 0; j < NT; j++) {
            const int gn = nB + wn * WN + j * 8 + (lane & 3) * 2;
            const float bi0 = __ldg(bias + gn), bi1 = __ldg(bias + gn + 1);
            float x0 = acc[i][j][0] + bi0, x1 = acc[i][j][1] + bi1;
            float x2 = acc[i][j][2] + bi0, x3 = acc[i][j][3] + bi1;
            if (MODE == MODE_ELU) {
                x0 = x0 > 0.0f ? x0 : expm1f(x0);
                x1 = x1 > 0.0f ? x1 : expm1f(x1);
                x2 = x2 > 0.0f ? x2 : expm1f(x2);
                x3 = x3 > 0.0f ? x3 : expm1f(x3);
            }
            const size_t g0 = (size_t)gm0 * N + gn;
            const size_t g1 = (size_t)(gm0 + 8) * N + gn;
            if (MODE == MODE_EULER) {
                float2 z0v = __ldcg((const float2*)(Zp + g0));
                float2 z1v = __ldcg((const float2*)(Zp + g1));
                x0 = z0v.x + h * x0; x1 = z0v.y + h * x1;
                x2 = z1v.x + h * x2; x3 = z1v.y + h * x3;
            }
            *(float2*)(C + g0) = make_float2(x0, x1);
            *(float2*)(C + g1) = make_float2(x2, x3);
        }
    }
}

// ---------------------------------------------------------------------------
// Persistent ODE integrator (grid = exactly NCTA x 256).
// Barriers per launch: 1 + 99*10*3 + 1 = 2972 (even -> g_sense ends at 0).
// ---------------------------------------------------------------------------
__global__ void __launch_bounds__(256, 1)
ode_persistent(const float* __restrict__ z0, const float* __restrict__ tv,
               const float* __restrict__ w1, const float* __restrict__ b1,
               const float* __restrict__ w2, const float* __restrict__ b2,
               const float* __restrict__ w3, const float* __restrict__ b3,
               float* __restrict__ zs, float* __restrict__ h1,
               float* __restrict__ h2, float* __restrict__ za,
               float* __restrict__ zb) {
    extern __shared__ float sm[];
    __shared__ unsigned s_sense;
    if (threadIdx.x == 0) s_sense = 0u;

    // zs[0] = z0
    for (int i = blockIdx.x * 256 + threadIdx.x; i < BATCH * LAT / 4; i += NCTA * 256)
        ((float4*)zs)[i] = __ldcg(((const float4*)z0) + i);
    grid_sync(&s_sense);                                    // barrier 1

    const int bx  = blockIdx.x;
    const int mB1 = (bx >> 3) * 128, nB1 = (bx & 7) * 128;  // 16x8 tiles of 128x128
    const int mB3 = (bx >> 2) * 64,  nB3 = (bx & 3) * 64;   // 32x4 tiles of 64x64
    const size_t BL = (size_t)BATCH * LAT;

    for (int it = 0; it < TSTEPS - 1; ++it) {
        const float hstep = (__ldg(tv + it + 1) - __ldg(tv + it)) * (1.0f / NSUB);
        for (int s = 0; s < NSUB; s++) {
            const float* zin  = (s == 0)        ? zs + (size_t)it * BL
                                                : ((s & 1) ? za : zb);
            float*       zout = (s == NSUB - 1) ? zs + (size_t)(it + 1) * BL
                                                : ((s & 1) ? zb : za);
            // h1 = elu(z @ w1.T + b1)   [2048x1024, K=256]
            tile_mma<128, 128, MODE_ELU>(zin, w1, b1, nullptr, h1,
                                         HID, LAT, 0.f, mB1, nB1, sm);
            grid_sync(&s_sense);
            // h2 = elu(h1 @ w2.T + b2)  [2048x1024, K=1024]
            tile_mma<128, 128, MODE_ELU>(h1, w2, b2, nullptr, h2,
                                         HID, HID, 0.f, mB1, nB1, sm);
            grid_sync(&s_sense);
            // zout = zin + h*(h2 @ w3.T + b3)  [2048x256, K=1024]
            tile_mma<64, 64, MODE_EULER>(h2, w3, b3, zin, zout,
                                         LAT, HID, hstep, mB3, nB3, sm);
            grid_sync(&s_sense);
        }
    }
    grid_sync(&s_sense);   // pad -> even count (2972)
}

// ---------------------------------------------------------------------------
// Folded decoder: out = zs @ Md.T + cd   (M=204800, N=512, K=256)
// ---------------------------------------------------------------------------
__global__ void __launch_bounds__(256, 1)
decoder_gemm(const float* __restrict__ zs, const float* __restrict__ Md,
             const float* __restrict__ cd, float* __restrict__ out) {
    extern __shared__ float sm[];
    tile_mma<128, 128, MODE_PLAIN>(zs, Md, cd, nullptr, out, OUTD, LAT, 0.f,
                                   blockIdx.y * 128, blockIdx.x * 128, sm);
}

// ---------------------------------------------------------------------------
// Decoder fold prep (tiny, once per launch)
// ---------------------------------------------------------------------------
__global__ void combine_kernel(const float* __restrict__ h2o_w,
                               const float* __restrict__ l2h_w,
                               float* __restrict__ Md) {
    __shared__ float sW[16][17];
    __shared__ float sL[16][17];
    const int o = blockIdx.y * 16 + threadIdx.y;
    const int l = blockIdx.x * 16 + threadIdx.x;
    float acc = 0.0f;
    for (int h0 = 0; h0 < HID; h0 += 16) {
        sW[threadIdx.y][threadIdx.x] = h2o_w[(size_t)o * HID + h0 + threadIdx.x];
        sL[threadIdx.y][threadIdx.x] = l2h_w[(size_t)(h0 + threadIdx.y) * LAT + l];
        __syncthreads();
#pragma unroll
        for (int kk = 0; kk < 16; kk++) acc += sW[threadIdx.y][kk] * sL[kk][threadIdx.x];
        __syncthreads();
    }
    Md[(size_t)o * LAT + l] = acc;
}

__global__ void cvec_kernel(const float* __restrict__ h2o_w,
                            const float* __restrict__ l2h_b,
                            const float* __restrict__ h2o_b,
                            float* __restrict__ cd) {
    const int o = blockIdx.x * blockDim.x + threadIdx.x;
    if (o < OUTD) {
        float a = h2o_b[o];
        for (int h = 0; h < HID; h++) a += h2o_w[(size_t)o * HID + h] * l2h_b[h];
        cd[o] = a;
    }
}

// ---------------------------------------------------------------------------
// 4 graph nodes: combine, cvec, persistent ODE, decoder.
// ---------------------------------------------------------------------------
extern "C" void kernel_launch(void* const* d_in, const int* in_sizes, int n_in,
                              void* d_out, int out_size) {
    const float* z0    = (const float*)d_in[0];
    const float* tv    = (const float*)d_in[1];
    const float* w1    = (const float*)d_in[2];
    const float* b1    = (const float*)d_in[3];
    const float* w2    = (const float*)d_in[4];
    const float* b2    = (const float*)d_in[5];
    const float* w3    = (const float*)d_in[6];
    const float* b3    = (const float*)d_in[7];
    const float* l2h_w = (const float*)d_in[8];
    const float* l2h_b = (const float*)d_in[9];
    const float* h2o_w = (const float*)d_in[10];
    const float* h2o_b = (const float*)d_in[11];
    float* out = (float*)d_out;

    float *zs, *h1, *h2, *za, *zb, *Md, *cd;
    cudaGetSymbolAddress((void**)&zs, g_zs);
    cudaGetSymbolAddress((void**)&h1, g_h1);
    cudaGetSymbolAddress((void**)&h2, g_h2);
    cudaGetSymbolAddress((void**)&za, g_za);
    cudaGetSymbolAddress((void**)&zb, g_zb);
    cudaGetSymbolAddress((void**)&Md, g_Md);
    cudaGetSymbolAddress((void**)&cd, g_cd);

    static bool attr_done = false;
    if (!attr_done) {
        cudaFuncSetAttribute(ode_persistent,
                             cudaFuncAttributeMaxDynamicSharedMemorySize, SMEM_BYTES);
        cudaFuncSetAttribute(decoder_gemm,
                             cudaFuncAttributeMaxDynamicSharedMemorySize, SMEM_BYTES);
        attr_done = true;
    }

    combine_kernel<<<dim3(LAT / 16, OUTD / 16), dim3(16, 16)>>>(h2o_w, l2h_w, Md);
    cvec_kernel<<<2, 256>>>(h2o_w, l2h_b, h2o_b, cd);

    ode_persistent<<<NCTA, 256, SMEM_BYTES>>>(z0, tv, w1, b1, w2, b2, w3, b3,
                                              zs, h1, h2, za, zb);

    decoder_gemm<<<dim3(OUTD / 128, TSTEPS * BATCH / 128), 256, SMEM_BYTES>>>(zs, Md, cd, out);
}

// round 6
// speedup vs baseline: 1.1949x; 1.1949x over previous
#include <cuda_runtime.h>
#include <math.h>
#include <cstdint>

// Problem constants
#define BATCH   2048
#define LAT     256
#define HID     1024
#define OUTD    512
#define TSTEPS  100
#define NSUB    10
#define NCTA    128
#define NTHR    512

enum { MODE_ELU = 0, MODE_EULER = 1, MODE_PLAIN = 2 };

// ---------------------------------------------------------------------------
// Device scratch (no cudaMalloc allowed)
// ---------------------------------------------------------------------------
__device__ __align__(256) float g_zs[(size_t)TSTEPS * BATCH * LAT];
__device__ __align__(256) float g_h1[(size_t)BATCH * HID];
__device__ __align__(256) float g_h2[(size_t)BATCH * HID];
__device__ __align__(256) float g_za[(size_t)BATCH * LAT];
__device__ __align__(256) float g_zb[(size_t)BATCH * LAT];
__device__ __align__(256) float g_Md[(size_t)OUTD * LAT];
__device__ __align__(256) float g_cd[OUTD];

// Pre-split weights (hi/lo tf32 stored as fp32 bit patterns)
__device__ __align__(256) float g_w1h[(size_t)HID * LAT],  g_w1l[(size_t)HID * LAT];
__device__ __align__(256) float g_w2h[(size_t)HID * HID],  g_w2l[(size_t)HID * HID];
__device__ __align__(256) float g_w3h[(size_t)LAT * HID],  g_w3l[(size_t)LAT * HID];
__device__ __align__(256) float g_Mdh[(size_t)OUTD * LAT], g_Mdl[(size_t)OUTD * LAT];

// grid-barrier state (returns to 0 each launch: even #barriers, count resets)
__device__ unsigned g_cnt;
__device__ unsigned g_sense;

// Dynamic smem: 4 tiles of 128 rows x 36 floats (stride-36; 144B rows are
// 16B-aligned so float4 STS works; scalar LDS bank = 4*(lane>>2)+(lane&3),
// a bijection -> conflict-free).
#define SA 36
#define TILE_FLOATS (128 * SA)
#define SMEM_BYTES (4 * TILE_FLOATS * 4)   // 73728 B

// ---------------------------------------------------------------------------
// Helpers
// ---------------------------------------------------------------------------
__device__ __forceinline__ float tf32_rna(float x) {
    uint32_t u;
    asm("cvt.rna.tf32.f32 %0, %1;" : "=r"(u) : "f"(x));
    return __uint_as_float(u);
}

// D += A*B (m16n8k8, tf32 inputs as bit patterns, fp32 accumulate)
__device__ __forceinline__ void mma8(float (&d)[4],
                                     float a0, float a1, float a2, float a3,
                                     float b0, float b1) {
    asm volatile(
        "mma.sync.aligned.m16n8k8.row.col.f32.tf32.tf32.f32 "
        "{%0,%1,%2,%3}, {%4,%5,%6,%7}, {%8,%9}, {%0,%1,%2,%3};"
        : "+f"(d[0]), "+f"(d[1]), "+f"(d[2]), "+f"(d[3])
        : "r"(__float_as_uint(a0)), "r"(__float_as_uint(a1)),
          "r"(__float_as_uint(a2)), "r"(__float_as_uint(a3)),
          "r"(__float_as_uint(b0)), "r"(__float_as_uint(b1)));
}

// ---------------------------------------------------------------------------
// Grid barrier: release/acquire at gpu scope (no MEMBAR.GPU, no L1D flush).
// ---------------------------------------------------------------------------
__device__ __forceinline__ void grid_sync(unsigned* s_sense) {
    __syncthreads();
    if (threadIdx.x == 0) {
        unsigned my = *s_sense ^ 1u;
        *s_sense = my;
        unsigned old;
        asm volatile("atom.release.gpu.global.add.u32 %0, [%1], %2;"
                     : "=r"(old) : "l"(&g_cnt), "r"(1u) : "memory");
        if (old == NCTA - 1u) {
            asm volatile("st.relaxed.gpu.global.u32 [%0], %1;" :: "l"(&g_cnt), "r"(0u) : "memory");
            asm volatile("st.release.gpu.global.u32 [%0], %1;" :: "l"(&g_sense), "r"(my) : "memory");
        } else {
            unsigned cur;
            do {
                asm volatile("ld.acquire.gpu.global.u32 %0, [%1];"
                             : "=r"(cur) : "l"(&g_sense) : "memory");
            } while (cur != my);
        }
    }
    __syncthreads();
}

// ---------------------------------------------------------------------------
// One BM x BN output tile:  C[m,n] = epilogue( sum_k A[m,k]*W[n,k] + bias[n] )
// 3-term tf32 split (AhBh + AhBl + AlBh), fp32 register accumulators.
// 512 threads = 16 warps (4x4 grid). A split on the fly; W pre-split (Wh/Wl).
// Layout identical to the proven R4 engine (stride-36 rows, scalar frag LDS).
// ---------------------------------------------------------------------------
template <int BM, int BN, int MODE>
__device__ __forceinline__ void tile_mma(
    const float* __restrict__ A,
    const float* __restrict__ Wh, const float* __restrict__ Wl,
    const float* __restrict__ bias, const float* __restrict__ Zp,
    float* __restrict__ C, int N, int K, float h,
    int mB, int nB, float* sm) {

    constexpr int WM  = BM / 4;        // warp tile M (4x4 warp grid)
    constexpr int WN  = BN / 4;        // warp tile N
    constexpr int MT  = WM / 16;       // mma tiles per warp (M)
    constexpr int NT  = WN / 8;        // mma tiles per warp (N)
    constexpr int APT = BM * 8 / NTHR; // A float4 per thread per chunk
    constexpr int BPT = BN * 8 / NTHR; // B float4 per thread per chunk

    float* sAh = sm;
    float* sAl = sm + TILE_FLOATS;
    float* sBh = sm + 2 * TILE_FLOATS;
    float* sBl = sm + 3 * TILE_FLOATS;

    const int tid  = threadIdx.x;
    const int lane = tid & 31;
    const int warp = tid >> 5;
    const int wm   = warp >> 2;        // 0..3
    const int wn   = warp & 3;         // 0..3
    const int nTc  = K >> 5;

    float4 ra[APT], rbh[BPT], rbl[BPT];
    float acc[MT][NT][4];
#pragma unroll
    for (int i = 0; i < MT; i++)
#pragma unroll
        for (int j = 0; j < NT; j++)
#pragma unroll
            for (int c = 0; c < 4; c++) acc[i][j][c] = 0.0f;

    auto ldg_chunk = [&](int t) {
#pragma unroll
        for (int i = 0; i < APT; i++) {
            int idx = tid + i * NTHR, row = idx >> 3, c4 = idx & 7;
            ra[i] = __ldcg((const float4*)(A + (size_t)(mB + row) * K + t * 32 + c4 * 4));
        }
#pragma unroll
        for (int i = 0; i < BPT; i++) {
            int idx = tid + i * NTHR, row = idx >> 3, c4 = idx & 7;
            const size_t o = (size_t)(nB + row) * K + t * 32 + c4 * 4;
            rbh[i] = __ldg((const float4*)(Wh + o));
            rbl[i] = __ldg((const float4*)(Wl + o));
        }
    };
    auto sts_chunk = [&]() {
#pragma unroll
        for (int i = 0; i < APT; i++) {
            int idx = tid + i * NTHR, row = idx >> 3, c4 = idx & 7;
            const int p = row * SA + c4 * 4;
            float4 v = ra[i], hi, lo;
            hi.x = tf32_rna(v.x); lo.x = tf32_rna(v.x - hi.x);
            hi.y = tf32_rna(v.y); lo.y = tf32_rna(v.y - hi.y);
            hi.z = tf32_rna(v.z); lo.z = tf32_rna(v.z - hi.z);
            hi.w = tf32_rna(v.w); lo.w = tf32_rna(v.w - hi.w);
            *(float4*)(sAh + p) = hi;
            *(float4*)(sAl + p) = lo;
        }
#pragma unroll
        for (int i = 0; i < BPT; i++) {
            int idx = tid + i * NTHR, row = idx >> 3, c4 = idx & 7;
            const int p = row * SA + c4 * 4;
            *(float4*)(sBh + p) = rbh[i];
            *(float4*)(sBl + p) = rbl[i];
        }
    };

    ldg_chunk(0);
    sts_chunk();
    __syncthreads();

    const int rA = wm * WM + (lane >> 2);
    const int rB = wn * WN + (lane >> 2);
    const int cK = lane & 3;

    for (int t = 0; t < nTc; ++t) {
        if (t + 1 < nTc) ldg_chunk(t + 1);

#pragma unroll
        for (int k8 = 0; k8 < 4; k8++) {
            const int kb = k8 * 8 + cK;
            float ah[MT][4], al[MT][4], bh[NT][2], bl[NT][2];
#pragma unroll
            for (int i = 0; i < MT; i++) {
                const int r0 = (rA + i * 16) * SA, r1 = r0 + 8 * SA;
                ah[i][0] = sAh[r0 + kb];
                ah[i][1] = sAh[r1 + kb];
                ah[i][2] = sAh[r0 + kb + 4];
                ah[i][3] = sAh[r1 + kb + 4];
                al[i][0] = sAl[r0 + kb];
                al[i][1] = sAl[r1 + kb];
                al[i][2] = sAl[r0 + kb + 4];
                al[i][3] = sAl[r1 + kb + 4];
            }
#pragma unroll
            for (int j = 0; j < NT; j++) {
                const int rn = (rB + j * 8) * SA;
                bh[j][0] = sBh[rn + kb];
                bh[j][1] = sBh[rn + kb + 4];
                bl[j][0] = sBl[rn + kb];
                bl[j][1] = sBl[rn + kb + 4];
            }
#pragma unroll
            for (int i = 0; i < MT; i++)
#pragma unroll
                for (int j = 0; j < NT; j++) {
                    mma8(acc[i][j], ah[i][0], ah[i][1], ah[i][2], ah[i][3], bh[j][0], bh[j][1]);
                    mma8(acc[i][j], ah[i][0], ah[i][1], ah[i][2], ah[i][3], bl[j][0], bl[j][1]);
                    mma8(acc[i][j], al[i][0], al[i][1], al[i][2], al[i][3], bh[j][0], bh[j][1]);
                }
        }

        __syncthreads();
        if (t + 1 < nTc) {
            sts_chunk();
            __syncthreads();
        }
    }

    // ---- epilogue: bias + mode, float2 stores straight from accumulators ----
#pragma unroll
    for (int i = 0; i < MT; i++) {
        const int gm0 = mB + wm * WM + i * 16 + (lane >> 2);
#pragma unroll
        for (int j = 0; j < NT; j++) {
            const int gn = nB + wn * WN + j * 8 + (lane & 3) * 2;
            const float bi0 = __ldg(bias + gn), bi1 = __ldg(bias + gn + 1);
            float x0 = acc[i][j][0] + bi0, x1 = acc[i][j][1] + bi1;
            float x2 = acc[i][j][2] + bi0, x3 = acc[i][j][3] + bi1;
            if (MODE == MODE_ELU) {
                x0 = x0 > 0.0f ? x0 : expm1f(x0);
                x1 = x1 > 0.0f ? x1 : expm1f(x1);
                x2 = x2 > 0.0f ? x2 : expm1f(x2);
                x3 = x3 > 0.0f ? x3 : expm1f(x3);
            }
            const size_t g0 = (size_t)gm0 * N + gn;
            const size_t g1 = (size_t)(gm0 + 8) * N + gn;
            if (MODE == MODE_EULER) {
                float2 z0v = __ldcg((const float2*)(Zp + g0));
                float2 z1v = __ldcg((const float2*)(Zp + g1));
                x0 = z0v.x + h * x0; x1 = z0v.y + h * x1;
                x2 = z1v.x + h * x2; x3 = z1v.y + h * x3;
            }
            *(float2*)(C + g0) = make_float2(x0, x1);
            *(float2*)(C + g1) = make_float2(x2, x3);
        }
    }
}

// ---------------------------------------------------------------------------
// Persistent ODE integrator (grid = exactly NCTA x 512 threads).
// Barriers per launch: 1 + 99*10*3 + 1 = 2972 (even -> g_sense ends at 0).
// ---------------------------------------------------------------------------
__global__ void __launch_bounds__(NTHR, 1)
ode_persistent(const float* __restrict__ z0, const float* __restrict__ tv,
               const float* __restrict__ b1, const float* __restrict__ b2,
               const float* __restrict__ b3,
               float* __restrict__ zs, float* __restrict__ h1,
               float* __restrict__ h2, float* __restrict__ za,
               float* __restrict__ zb) {
    extern __shared__ float sm[];
    __shared__ unsigned s_sense;
    if (threadIdx.x == 0) s_sense = 0u;

    // zs[0] = z0
    for (int i = blockIdx.x * NTHR + threadIdx.x; i < BATCH * LAT / 4; i += NCTA * NTHR)
        ((float4*)zs)[i] = __ldcg(((const float4*)z0) + i);
    grid_sync(&s_sense);                                    // barrier 1

    const int bx  = blockIdx.x;
    const int mB1 = (bx >> 3) * 128, nB1 = (bx & 7) * 128;  // 16x8 tiles of 128x128
    const int mB3 = (bx >> 2) * 64,  nB3 = (bx & 3) * 64;   // 32x4 tiles of 64x64
    const size_t BL = (size_t)BATCH * LAT;

    for (int it = 0; it < TSTEPS - 1; ++it) {
        const float hstep = (__ldg(tv + it + 1) - __ldg(tv + it)) * (1.0f / NSUB);
        for (int s = 0; s < NSUB; s++) {
            const float* zin  = (s == 0)        ? zs + (size_t)it * BL
                                                : ((s & 1) ? za : zb);
            float*       zout = (s == NSUB - 1) ? zs + (size_t)(it + 1) * BL
                                                : ((s & 1) ? zb : za);
            // h1 = elu(z @ w1.T + b1)   [2048x1024, K=256]
            tile_mma<128, 128, MODE_ELU>(zin, g_w1h, g_w1l, b1, nullptr, h1,
                                         HID, LAT, 0.f, mB1, nB1, sm);
            grid_sync(&s_sense);
            // h2 = elu(h1 @ w2.T + b2)  [2048x1024, K=1024]
            tile_mma<128, 128, MODE_ELU>(h1, g_w2h, g_w2l, b2, nullptr, h2,
                                         HID, HID, 0.f, mB1, nB1, sm);
            grid_sync(&s_sense);
            // zout = zin + h*(h2 @ w3.T + b3)  [2048x256, K=1024]
            tile_mma<64, 64, MODE_EULER>(h2, g_w3h, g_w3l, b3, zin, zout,
                                         LAT, HID, hstep, mB3, nB3, sm);
            grid_sync(&s_sense);
        }
    }
    grid_sync(&s_sense);   // pad -> even count (2972)
}

// ---------------------------------------------------------------------------
// Folded decoder: out = zs @ Md.T + cd   (M=204800, N=512, K=256)
// ---------------------------------------------------------------------------
__global__ void __launch_bounds__(NTHR, 1)
decoder_gemm(const float* __restrict__ zs, const float* __restrict__ cd,
             float* __restrict__ out) {
    extern __shared__ float sm[];
    tile_mma<128, 128, MODE_PLAIN>(zs, g_Mdh, g_Mdl, cd, nullptr, out,
                                   OUTD, LAT, 0.f,
                                   blockIdx.y * 128, blockIdx.x * 128, sm);
}

// ---------------------------------------------------------------------------
// Prep: decoder fold + tf32 hi/lo weight splits (tiny, once per launch)
// ---------------------------------------------------------------------------
__global__ void combine_kernel(const float* __restrict__ h2o_w,
                               const float* __restrict__ l2h_w,
                               float* __restrict__ Md) {
    __shared__ float sW[16][17];
    __shared__ float sL[16][17];
    const int o = blockIdx.y * 16 + threadIdx.y;
    const int l = blockIdx.x * 16 + threadIdx.x;
    float acc = 0.0f;
    for (int h0 = 0; h0 < HID; h0 += 16) {
        sW[threadIdx.y][threadIdx.x] = h2o_w[(size_t)o * HID + h0 + threadIdx.x];
        sL[threadIdx.y][threadIdx.x] = l2h_w[(size_t)(h0 + threadIdx.y) * LAT + l];
        __syncthreads();
#pragma unroll
        for (int kk = 0; kk < 16; kk++) acc += sW[threadIdx.y][kk] * sL[kk][threadIdx.x];
        __syncthreads();
    }
    Md[(size_t)o * LAT + l] = acc;
}

__global__ void cvec_kernel(const float* __restrict__ h2o_w,
                            const float* __restrict__ l2h_b,
                            const float* __restrict__ h2o_b,
                            float* __restrict__ cd) {
    const int o = blockIdx.x * blockDim.x + threadIdx.x;
    if (o < OUTD) {
        float a = h2o_b[o];
        for (int h = 0; h < HID; h++) a += h2o_w[(size_t)o * HID + h] * l2h_b[h];
        cd[o] = a;
    }
}

__global__ void split_kernel(const float* __restrict__ w,
                             float* __restrict__ wh, float* __restrict__ wl, int n) {
    const int i = blockIdx.x * blockDim.x + threadIdx.x;
    if (i < n) {
        float x = w[i];
        float hi = tf32_rna(x);
        wh[i] = hi;
        wl[i] = tf32_rna(x - hi);
    }
}

// ---------------------------------------------------------------------------
// Graph nodes: combine, cvec, 4x split, persistent ODE, decoder.
// ---------------------------------------------------------------------------
extern "C" void kernel_launch(void* const* d_in, const int* in_sizes, int n_in,
                              void* d_out, int out_size) {
    const float* z0    = (const float*)d_in[0];
    const float* tv    = (const float*)d_in[1];
    const float* w1    = (const float*)d_in[2];
    const float* b1    = (const float*)d_in[3];
    const float* w2    = (const float*)d_in[4];
    const float* b2    = (const float*)d_in[5];
    const float* w3    = (const float*)d_in[6];
    const float* b3    = (const float*)d_in[7];
    const float* l2h_w = (const float*)d_in[8];
    const float* l2h_b = (const float*)d_in[9];
    const float* h2o_w = (const float*)d_in[10];
    const float* h2o_b = (const float*)d_in[11];
    float* out = (float*)d_out;

    float *zs, *h1, *h2, *za, *zb, *Md, *cd;
    float *w1h, *w1l, *w2h, *w2l, *w3h, *w3l, *Mdh, *Mdl;
    cudaGetSymbolAddress((void**)&zs, g_zs);
    cudaGetSymbolAddress((void**)&h1, g_h1);
    cudaGetSymbolAddress((void**)&h2, g_h2);
    cudaGetSymbolAddress((void**)&za, g_za);
    cudaGetSymbolAddress((void**)&zb, g_zb);
    cudaGetSymbolAddress((void**)&Md, g_Md);
    cudaGetSymbolAddress((void**)&cd, g_cd);
    cudaGetSymbolAddress((void**)&w1h, g_w1h);
    cudaGetSymbolAddress((void**)&w1l, g_w1l);
    cudaGetSymbolAddress((void**)&w2h, g_w2h);
    cudaGetSymbolAddress((void**)&w2l, g_w2l);
    cudaGetSymbolAddress((void**)&w3h, g_w3h);
    cudaGetSymbolAddress((void**)&w3l, g_w3l);
    cudaGetSymbolAddress((void**)&Mdh, g_Mdh);
    cudaGetSymbolAddress((void**)&Mdl, g_Mdl);

    static bool attr_done = false;
    if (!attr_done) {
        cudaFuncSetAttribute(ode_persistent,
                             cudaFuncAttributeMaxDynamicSharedMemorySize, SMEM_BYTES);
        cudaFuncSetAttribute(decoder_gemm,
                             cudaFuncAttributeMaxDynamicSharedMemorySize, SMEM_BYTES);
        attr_done = true;
    }

    // prep: decoder fold + weight splits
    combine_kernel<<<dim3(LAT / 16, OUTD / 16), dim3(16, 16)>>>(h2o_w, l2h_w, Md);
    cvec_kernel<<<2, 256>>>(h2o_w, l2h_b, h2o_b, cd);
    split_kernel<<<(HID * LAT + 255) / 256, 256>>>(w1, w1h, w1l, HID * LAT);
    split_kernel<<<(HID * HID + 255) / 256, 256>>>(w2, w2h, w2l, HID * HID);
    split_kernel<<<(LAT * HID + 255) / 256, 256>>>(w3, w3h, w3l, LAT * HID);
    split_kernel<<<(OUTD * LAT + 255) / 256, 256>>>(Md, Mdh, Mdl, OUTD * LAT);

    ode_persistent<<<NCTA, NTHR, SMEM_BYTES>>>(z0, tv, b1, b2, b3,
                                               zs, h1, h2, za, zb);

    decoder_gemm<<<dim3(OUTD / 128, TSTEPS * BATCH / 128), NTHR, SMEM_BYTES>>>(zs, cd, out);
}

// round 7
// speedup vs baseline: 1.2585x; 1.0532x over previous
#include <cuda_runtime.h>
#include <math.h>
#include <cstdint>

// Problem constants
#define BATCH   2048
#define LAT     256
#define HID     1024
#define OUTD    512
#define TSTEPS  100
#define NSUB    10
#define NCTA    128
#define NTHR    256

enum { MODE_ELU = 0, MODE_EULER = 1, MODE_PLAIN = 2 };

// ---------------------------------------------------------------------------
// Device scratch (no cudaMalloc allowed)
// ---------------------------------------------------------------------------
__device__ __align__(256) float g_zs[(size_t)TSTEPS * BATCH * LAT];
__device__ __align__(256) float g_h1[(size_t)BATCH * HID];
__device__ __align__(256) float g_h2[(size_t)BATCH * HID];
__device__ __align__(256) float g_za[(size_t)BATCH * LAT];
__device__ __align__(256) float g_zb[(size_t)BATCH * LAT];
__device__ __align__(256) float g_Md[(size_t)OUTD * LAT];
__device__ __align__(256) float g_cd[OUTD];

// Pre-split weights (hi/lo tf32 stored as fp32 bit patterns)
__device__ __align__(256) float g_w1h[(size_t)HID * LAT],  g_w1l[(size_t)HID * LAT];
__device__ __align__(256) float g_w2h[(size_t)HID * HID],  g_w2l[(size_t)HID * HID];
__device__ __align__(256) float g_w3h[(size_t)LAT * HID],  g_w3l[(size_t)LAT * HID];
__device__ __align__(256) float g_Mdh[(size_t)OUTD * LAT], g_Mdl[(size_t)OUTD * LAT];

// grid-barrier state (returns to 0 each launch: even #barriers, count resets)
__device__ unsigned g_cnt;
__device__ unsigned g_sense;

// Smem: 2 buffers x 4 tiles x 128 rows x 36 floats (stride-36: scalar LDS
// bank = 4*(lane>>2)+(lane&3), a bijection -> conflict-free; rows 144B so
// 16B-aligned float4/cp.async chunks).
#define SA       36
#define TILE_F   (128 * SA)          // floats per tile
#define BUF_F    (4 * TILE_F)        // floats per buffer
#define SMEM_BYTES (2 * BUF_F * 4)   // 147456 B

// ---------------------------------------------------------------------------
// Helpers
// ---------------------------------------------------------------------------
__device__ __forceinline__ float tf32_rna(float x) {
    uint32_t u;
    asm("cvt.rna.tf32.f32 %0, %1;" : "=r"(u) : "f"(x));
    return __uint_as_float(u);
}

__device__ __forceinline__ uint32_t smem_u32(const void* p) {
    uint32_t a;
    asm("{ .reg .u64 t; cvta.to.shared.u64 t, %1; cvt.u32.u64 %0, t; }" : "=r"(a) : "l"(p));
    return a;
}

__device__ __forceinline__ void cp16(uint32_t dst, const void* src) {
    asm volatile("cp.async.cg.shared.global [%0], [%1], 16;" :: "r"(dst), "l"(src));
}
#define CP_COMMIT() asm volatile("cp.async.commit_group;" ::: "memory")
#define CP_WAIT0()  asm volatile("cp.async.wait_group 0;" ::: "memory")

// D += A*B (m16n8k8, tf32 inputs as bit patterns, fp32 accumulate)
__device__ __forceinline__ void mma8(float (&d)[4],
                                     float a0, float a1, float a2, float a3,
                                     float b0, float b1) {
    asm volatile(
        "mma.sync.aligned.m16n8k8.row.col.f32.tf32.tf32.f32 "
        "{%0,%1,%2,%3}, {%4,%5,%6,%7}, {%8,%9}, {%0,%1,%2,%3};"
        : "+f"(d[0]), "+f"(d[1]), "+f"(d[2]), "+f"(d[3])
        : "r"(__float_as_uint(a0)), "r"(__float_as_uint(a1)),
          "r"(__float_as_uint(a2)), "r"(__float_as_uint(a3)),
          "r"(__float_as_uint(b0)), "r"(__float_as_uint(b1)));
}

// ---------------------------------------------------------------------------
// Grid barrier: release/acquire at gpu scope (no MEMBAR.GPU, no L1D flush).
// ---------------------------------------------------------------------------
__device__ __forceinline__ void grid_sync(unsigned* s_sense) {
    __syncthreads();
    if (threadIdx.x == 0) {
        unsigned my = *s_sense ^ 1u;
        *s_sense = my;
        unsigned old;
        asm volatile("atom.release.gpu.global.add.u32 %0, [%1], %2;"
                     : "=r"(old) : "l"(&g_cnt), "r"(1u) : "memory");
        if (old == NCTA - 1u) {
            asm volatile("st.relaxed.gpu.global.u32 [%0], %1;" :: "l"(&g_cnt), "r"(0u) : "memory");
            asm volatile("st.release.gpu.global.u32 [%0], %1;" :: "l"(&g_sense), "r"(my) : "memory");
        } else {
            unsigned cur;
            do {
                asm volatile("ld.acquire.gpu.global.u32 %0, [%1];"
                             : "=r"(cur) : "l"(&g_sense) : "memory");
            } while (cur != my);
        }
    }
    __syncthreads();
}

// ---------------------------------------------------------------------------
// One BM x BN output tile:  C[m,n] = epilogue( sum_k A[m,k]*W[n,k] + bias[n] )
// 3-term tf32 split (AhBh + AhBl + AlBh), fp32 register accumulators.
// 256 threads = 8 warps (2x4 grid), warp tile (BM/2)x(BN/4).
// Double-buffered smem; A split on the fly (LDG->regs->STS); B tiles pulled
// straight from pre-split global weights via cp.async (no register staging).
// ---------------------------------------------------------------------------
template <int BM, int BN, int MODE>
__device__ __forceinline__ void tile_mma(
    const float* __restrict__ A,
    const float* __restrict__ Wh, const float* __restrict__ Wl,
    const float* __restrict__ bias, const float* __restrict__ Zp,
    float* __restrict__ C, int N, int K, float h,
    int mB, int nB, float* sm, uint32_t smb) {

    constexpr int MT  = BM / 32;       // mma tiles per warp (M): 4 or 2
    constexpr int NT  = BN / 32;       // mma tiles per warp (N): 4 or 2
    constexpr int WM  = MT * 16;       // warp tile M
    constexpr int WN  = NT * 8;        // warp tile N
    constexpr int APT = BM * 8 / NTHR; // A float4 per thread per chunk
    constexpr int BPT = BN * 8 / NTHR; // B float4 per thread per chunk

    const int tid  = threadIdx.x;
    const int lane = tid & 31;
    const int warp = tid >> 5;
    const int wmi  = warp >> 2;        // 0..1
    const int wni  = warp & 3;         // 0..3
    const int nTc  = K >> 5;

    float4 ra[APT];
    float acc[MT][NT][4];
#pragma unroll
    for (int i = 0; i < MT; i++)
#pragma unroll
        for (int j = 0; j < NT; j++)
#pragma unroll
            for (int c = 0; c < 4; c++) acc[i][j][c] = 0.0f;

    auto ldgA = [&](int t) {
#pragma unroll
        for (int i = 0; i < APT; i++) {
            int idx = tid + i * NTHR, row = idx >> 3, c4 = idx & 7;
            ra[i] = __ldcg((const float4*)(A + (size_t)(mB + row) * K + t * 32 + c4 * 4));
        }
    };
    auto cpB = [&](int t, int b) {
        const uint32_t base = smb + (uint32_t)b * (BUF_F * 4) + 2 * (TILE_F * 4);
#pragma unroll
        for (int i = 0; i < BPT; i++) {
            int idx = tid + i * NTHR, row = idx >> 3, c4 = idx & 7;
            const size_t o = (size_t)(nB + row) * K + t * 32 + c4 * 4;
            const uint32_t d = base + (uint32_t)(row * SA + c4 * 4) * 4;
            cp16(d, Wh + o);
            cp16(d + TILE_F * 4, Wl + o);
        }
        CP_COMMIT();
    };
    auto stsA = [&](int b) {
        float* sAh = sm + b * BUF_F;
        float* sAl = sAh + TILE_F;
#pragma unroll
        for (int i = 0; i < APT; i++) {
            int idx = tid + i * NTHR, row = idx >> 3, c4 = idx & 7;
            const int p = row * SA + c4 * 4;
            float4 v = ra[i], hi, lo;
            hi.x = tf32_rna(v.x); lo.x = tf32_rna(v.x - hi.x);
            hi.y = tf32_rna(v.y); lo.y = tf32_rna(v.y - hi.y);
            hi.z = tf32_rna(v.z); lo.z = tf32_rna(v.z - hi.z);
            hi.w = tf32_rna(v.w); lo.w = tf32_rna(v.w - hi.w);
            *(float4*)(sAh + p) = hi;
            *(float4*)(sAl + p) = lo;
        }
    };

    // prologue: fill buffer 0
    ldgA(0);
    cpB(0, 0);
    stsA(0);
    CP_WAIT0();
    __syncthreads();

    const int rA = wmi * WM + (lane >> 2);
    const int rB = wni * WN + (lane >> 2);
    const int cK = lane & 3;

    for (int t = 0; t < nTc; ++t) {
        const int cur = t & 1, nxt = cur ^ 1;
        if (t + 1 < nTc) {
            ldgA(t + 1);       // global latency overlaps mma below
            cpB(t + 1, nxt);   // B streams straight into the other buffer
        }

        const float* sAh = sm + cur * BUF_F;
        const float* sAl = sAh + TILE_F;
        const float* sBh = sAl + TILE_F;
        const float* sBl = sBh + TILE_F;

#pragma unroll
        for (int k8 = 0; k8 < 4; k8++) {
            const int kb = k8 * 8 + cK;
            float ah[MT][4], al[MT][4], bh[NT][2], bl[NT][2];
#pragma unroll
            for (int i = 0; i < MT; i++) {
                const int r0 = (rA + i * 16) * SA, r1 = r0 + 8 * SA;
                ah[i][0] = sAh[r0 + kb];
                ah[i][1] = sAh[r1 + kb];
                ah[i][2] = sAh[r0 + kb + 4];
                ah[i][3] = sAh[r1 + kb + 4];
                al[i][0] = sAl[r0 + kb];
                al[i][1] = sAl[r1 + kb];
                al[i][2] = sAl[r0 + kb + 4];
                al[i][3] = sAl[r1 + kb + 4];
            }
#pragma unroll
            for (int j = 0; j < NT; j++) {
                const int rn = (rB + j * 8) * SA;
                bh[j][0] = sBh[rn + kb];
                bh[j][1] = sBh[rn + kb + 4];
                bl[j][0] = sBl[rn + kb];
                bl[j][1] = sBl[rn + kb + 4];
            }
#pragma unroll
            for (int i = 0; i < MT; i++)
#pragma unroll
                for (int j = 0; j < NT; j++) {
                    mma8(acc[i][j], ah[i][0], ah[i][1], ah[i][2], ah[i][3], bh[j][0], bh[j][1]);
                    mma8(acc[i][j], ah[i][0], ah[i][1], ah[i][2], ah[i][3], bl[j][0], bl[j][1]);
                    mma8(acc[i][j], al[i][0], al[i][1], al[i][2], al[i][3], bh[j][0], bh[j][1]);
                }
        }

        if (t + 1 < nTc) {
            stsA(nxt);        // into the other buffer: no race with readers of cur
            CP_WAIT0();       // B(t+1) landed
            __syncthreads();  // one barrier per chunk
        }
    }

    // ---- epilogue: bias + mode, float2 stores straight from accumulators ----
#pragma unroll
    for (int i = 0; i < MT; i++) {
        const int gm0 = mB + wmi * WM + i * 16 + (lane >> 2);
#pragma unroll
        for (int j = 0; j < NT; j++) {
            const int gn = nB + wni * WN + j * 8 + (lane & 3) * 2;
            const float bi0 = __ldg(bias + gn), bi1 = __ldg(bias + gn + 1);
            float x0 = acc[i][j][0] + bi0, x1 = acc[i][j][1] + bi1;
            float x2 = acc[i][j][2] + bi0, x3 = acc[i][j][3] + bi1;
            if (MODE == MODE_ELU) {
                x0 = x0 > 0.0f ? x0 : expm1f(x0);
                x1 = x1 > 0.0f ? x1 : expm1f(x1);
                x2 = x2 > 0.0f ? x2 : expm1f(x2);
                x3 = x3 > 0.0f ? x3 : expm1f(x3);
            }
            const size_t g0 = (size_t)gm0 * N + gn;
            const size_t g1 = (size_t)(gm0 + 8) * N + gn;
            if (MODE == MODE_EULER) {
                float2 z0v = __ldcg((const float2*)(Zp + g0));
                float2 z1v = __ldcg((const float2*)(Zp + g1));
                x0 = z0v.x + h * x0; x1 = z0v.y + h * x1;
                x2 = z1v.x + h * x2; x3 = z1v.y + h * x3;
            }
            *(float2*)(C + g0) = make_float2(x0, x1);
            *(float2*)(C + g1) = make_float2(x2, x3);
        }
    }
}

// ---------------------------------------------------------------------------
// Persistent ODE integrator (grid = exactly NCTA x 256 threads).
// Barriers per launch: 1 + 99*10*3 + 1 = 2972 (even -> g_sense ends at 0).
// ---------------------------------------------------------------------------
__global__ void __launch_bounds__(NTHR, 1)
ode_persistent(const float* __restrict__ z0, const float* __restrict__ tv,
               const float* __restrict__ b1, const float* __restrict__ b2,
               const float* __restrict__ b3,
               float* __restrict__ zs, float* __restrict__ h1,
               float* __restrict__ h2, float* __restrict__ za,
               float* __restrict__ zb) {
    extern __shared__ float sm[];
    const uint32_t smb = smem_u32(sm);
    __shared__ unsigned s_sense;
    if (threadIdx.x == 0) s_sense = 0u;

    // zs[0] = z0
    for (int i = blockIdx.x * NTHR + threadIdx.x; i < BATCH * LAT / 4; i += NCTA * NTHR)
        ((float4*)zs)[i] = __ldcg(((const float4*)z0) + i);
    grid_sync(&s_sense);                                    // barrier 1

    const int bx  = blockIdx.x;
    const int mB1 = (bx >> 3) * 128, nB1 = (bx & 7) * 128;  // 16x8 tiles of 128x128
    const int mB3 = (bx >> 2) * 64,  nB3 = (bx & 3) * 64;   // 32x4 tiles of 64x64
    const size_t BL = (size_t)BATCH * LAT;

    for (int it = 0; it < TSTEPS - 1; ++it) {
        const float hstep = (__ldg(tv + it + 1) - __ldg(tv + it)) * (1.0f / NSUB);
        for (int s = 0; s < NSUB; s++) {
            const float* zin  = (s == 0)        ? zs + (size_t)it * BL
                                                : ((s & 1) ? za : zb);
            float*       zout = (s == NSUB - 1) ? zs + (size_t)(it + 1) * BL
                                                : ((s & 1) ? zb : za);
            // h1 = elu(z @ w1.T + b1)   [2048x1024, K=256]
            tile_mma<128, 128, MODE_ELU>(zin, g_w1h, g_w1l, b1, nullptr, h1,
                                         HID, LAT, 0.f, mB1, nB1, sm, smb);
            grid_sync(&s_sense);
            // h2 = elu(h1 @ w2.T + b2)  [2048x1024, K=1024]
            tile_mma<128, 128, MODE_ELU>(h1, g_w2h, g_w2l, b2, nullptr, h2,
                                         HID, HID, 0.f, mB1, nB1, sm, smb);
            grid_sync(&s_sense);
            // zout = zin + h*(h2 @ w3.T + b3)  [2048x256, K=1024]
            tile_mma<64, 64, MODE_EULER>(h2, g_w3h, g_w3l, b3, zin, zout,
                                         LAT, HID, hstep, mB3, nB3, sm, smb);
            grid_sync(&s_sense);
        }
    }
    grid_sync(&s_sense);   // pad -> even count (2972)
}

// ---------------------------------------------------------------------------
// Folded decoder: out = zs @ Md.T + cd   (M=204800, N=512, K=256)
// ---------------------------------------------------------------------------
__global__ void __launch_bounds__(NTHR, 1)
decoder_gemm(const float* __restrict__ zs, const float* __restrict__ cd,
             float* __restrict__ out) {
    extern __shared__ float sm[];
    const uint32_t smb = smem_u32(sm);
    tile_mma<128, 128, MODE_PLAIN>(zs, g_Mdh, g_Mdl, cd, nullptr, out,
                                   OUTD, LAT, 0.f,
                                   blockIdx.y * 128, blockIdx.x * 128, sm, smb);
}

// ---------------------------------------------------------------------------
// Prep: decoder fold + tf32 hi/lo weight splits (tiny, once per launch)
// ---------------------------------------------------------------------------
__global__ void combine_kernel(const float* __restrict__ h2o_w,
                               const float* __restrict__ l2h_w,
                               float* __restrict__ Md) {
    __shared__ float sW[16][17];
    __shared__ float sL[16][17];
    const int o = blockIdx.y * 16 + threadIdx.y;
    const int l = blockIdx.x * 16 + threadIdx.x;
    float acc = 0.0f;
    for (int h0 = 0; h0 < HID; h0 += 16) {
        sW[threadIdx.y][threadIdx.x] = h2o_w[(size_t)o * HID + h0 + threadIdx.x];
        sL[threadIdx.y][threadIdx.x] = l2h_w[(size_t)(h0 + threadIdx.y) * LAT + l];
        __syncthreads();
#pragma unroll
        for (int kk = 0; kk < 16; kk++) acc += sW[threadIdx.y][kk] * sL[kk][threadIdx.x];
        __syncthreads();
    }
    Md[(size_t)o * LAT + l] = acc;
}

__global__ void cvec_kernel(const float* __restrict__ h2o_w,
                            const float* __restrict__ l2h_b,
                            const float* __restrict__ h2o_b,
                            float* __restrict__ cd) {
    const int o = blockIdx.x * blockDim.x + threadIdx.x;
    if (o < OUTD) {
        float a = h2o_b[o];
        for (int h = 0; h < HID; h++) a += h2o_w[(size_t)o * HID + h] * l2h_b[h];
        cd[o] = a;
    }
}

__global__ void split_kernel(const float* __restrict__ w,
                             float* __restrict__ wh, float* __restrict__ wl, int n) {
    const int i = blockIdx.x * blockDim.x + threadIdx.x;
    if (i < n) {
        float x = w[i];
        float hi = tf32_rna(x);
        wh[i] = hi;
        wl[i] = tf32_rna(x - hi);
    }
}

// ---------------------------------------------------------------------------
// Graph nodes: combine, cvec, 4x split, persistent ODE, decoder.
// ---------------------------------------------------------------------------
extern "C" void kernel_launch(void* const* d_in, const int* in_sizes, int n_in,
                              void* d_out, int out_size) {
    const float* z0    = (const float*)d_in[0];
    const float* tv    = (const float*)d_in[1];
    const float* w1    = (const float*)d_in[2];
    const float* b1    = (const float*)d_in[3];
    const float* w2    = (const float*)d_in[4];
    const float* b2    = (const float*)d_in[5];
    const float* w3    = (const float*)d_in[6];
    const float* b3    = (const float*)d_in[7];
    const float* l2h_w = (const float*)d_in[8];
    const float* l2h_b = (const float*)d_in[9];
    const float* h2o_w = (const float*)d_in[10];
    const float* h2o_b = (const float*)d_in[11];
    float* out = (float*)d_out;

    float *zs, *h1, *h2, *za, *zb, *Md, *cd;
    float *w1h, *w1l, *w2h, *w2l, *w3h, *w3l, *Mdh, *Mdl;
    cudaGetSymbolAddress((void**)&zs, g_zs);
    cudaGetSymbolAddress((void**)&h1, g_h1);
    cudaGetSymbolAddress((void**)&h2, g_h2);
    cudaGetSymbolAddress((void**)&za, g_za);
    cudaGetSymbolAddress((void**)&zb, g_zb);
    cudaGetSymbolAddress((void**)&Md, g_Md);
    cudaGetSymbolAddress((void**)&cd, g_cd);
    cudaGetSymbolAddress((void**)&w1h, g_w1h);
    cudaGetSymbolAddress((void**)&w1l, g_w1l);
    cudaGetSymbolAddress((void**)&w2h, g_w2h);
    cudaGetSymbolAddress((void**)&w2l, g_w2l);
    cudaGetSymbolAddress((void**)&w3h, g_w3h);
    cudaGetSymbolAddress((void**)&w3l, g_w3l);
    cudaGetSymbolAddress((void**)&Mdh, g_Mdh);
    cudaGetSymbolAddress((void**)&Mdl, g_Mdl);

    static bool attr_done = false;
    if (!attr_done) {
        cudaFuncSetAttribute(ode_persistent,
                             cudaFuncAttributeMaxDynamicSharedMemorySize, SMEM_BYTES);
        cudaFuncSetAttribute(decoder_gemm,
                             cudaFuncAttributeMaxDynamicSharedMemorySize, SMEM_BYTES);
        attr_done = true;
    }

    // prep: decoder fold + weight splits
    combine_kernel<<<dim3(LAT / 16, OUTD / 16), dim3(16, 16)>>>(h2o_w, l2h_w, Md);
    cvec_kernel<<<2, 256>>>(h2o_w, l2h_b, h2o_b, cd);
    split_kernel<<<(HID * LAT + 255) / 256, 256>>>(w1, w1h, w1l, HID * LAT);
    split_kernel<<<(HID * HID + 255) / 256, 256>>>(w2, w2h, w2l, HID * HID);
    split_kernel<<<(LAT * HID + 255) / 256, 256>>>(w3, w3h, w3l, LAT * HID);
    split_kernel<<<(OUTD * LAT + 255) / 256, 256>>>(Md, Mdh, Mdl, OUTD * LAT);

    ode_persistent<<<NCTA, NTHR, SMEM_BYTES>>>(z0, tv, b1, b2, b3,
                                               zs, h1, h2, za, zb);

    decoder_gemm<<<dim3(OUTD / 128, TSTEPS * BATCH / 128), NTHR, SMEM_BYTES>>>(zs, cd, out);
}

// round 9
// speedup vs baseline: 1.7020x; 1.3524x over previous
#include <cuda_runtime.h>
#include <cuda_fp16.h>
#include <math.h>
#include <cstdint>

// Problem constants
#define BATCH   2048
#define LAT     256
#define HID     1024
#define OUTD    512
#define TSTEPS  100
#define NSUB    10
#define NCTA    128
#define NTHR    256

enum { MODE_ELU = 0, MODE_EULER = 1, MODE_PLAIN = 2 };

// ---------------------------------------------------------------------------
// Device scratch (no cudaMalloc allowed)
// ---------------------------------------------------------------------------
__device__ __align__(256) float g_zs[(size_t)TSTEPS * BATCH * LAT];
__device__ __align__(256) float g_h1[(size_t)BATCH * HID];
__device__ __align__(256) float g_h2[(size_t)BATCH * HID];
__device__ __align__(256) float g_za[(size_t)BATCH * LAT];
__device__ __align__(256) float g_zb[(size_t)BATCH * LAT];
__device__ __align__(256) float g_Md[(size_t)OUTD * LAT];
__device__ __align__(256) float g_cd[OUTD];

// Pre-split weights: fp16 hi/lo (hi = rn(x), lo = rn(x - hi))
__device__ __align__(256) __half g_w1h[(size_t)HID * LAT],  g_w1l[(size_t)HID * LAT];
__device__ __align__(256) __half g_w2h[(size_t)HID * HID],  g_w2l[(size_t)HID * HID];
__device__ __align__(256) __half g_w3h[(size_t)LAT * HID],  g_w3l[(size_t)LAT * HID];
__device__ __align__(256) __half g_Mdh[(size_t)OUTD * LAT], g_Mdl[(size_t)OUTD * LAT];

// grid-barrier state (returns to 0 each launch: even #barriers, count resets)
__device__ unsigned g_cnt;
__device__ unsigned g_sense;

// Smem: 2 buffers x 4 tiles (Ah,Al,Bh,Bl); tile = 128 rows x 36 half2
// (rows are 16 half2 of payload + padding; stride 36 proven conflict-free for
// both 16B STS and scalar 4B frag LDS: bank = 4*(lane>>2)+(lane&3) bijection).
#define SA       36                    // half2 per row
#define TILE_H   (128 * SA)            // half2 per tile
#define BUF_H    (4 * TILE_H)          // half2 per buffer
#define TILE_B   (TILE_H * 4)          // bytes per tile
#define SMEM_BYTES (2 * BUF_H * 4)     // 147456 B

// ---------------------------------------------------------------------------
// Helpers
// ---------------------------------------------------------------------------
__device__ __forceinline__ uint32_t smem_u32(const void* p) {
    uint32_t a;
    asm("{ .reg .u64 t; cvta.to.shared.u64 t, %1; cvt.u32.u64 %0, t; }" : "=r"(a) : "l"(p));
    return a;
}

__device__ __forceinline__ void cp16(uint32_t dst, const void* src) {
    asm volatile("cp.async.cg.shared.global [%0], [%1], 16;" :: "r"(dst), "l"(src));
}
#define CP_COMMIT() asm volatile("cp.async.commit_group;" ::: "memory")
#define CP_WAIT0()  asm volatile("cp.async.wait_group 0;" ::: "memory")

// D += A*B (m16n8k16 fp16 inputs, fp32 accumulate)
__device__ __forceinline__ void mma16(float (&d)[4],
                                      uint32_t a0, uint32_t a1, uint32_t a2, uint32_t a3,
                                      uint32_t b0, uint32_t b1) {
    asm volatile(
        "mma.sync.aligned.m16n8k16.row.col.f32.f16.f16.f32 "
        "{%0,%1,%2,%3}, {%4,%5,%6,%7}, {%8,%9}, {%0,%1,%2,%3};"
        : "+f"(d[0]), "+f"(d[1]), "+f"(d[2]), "+f"(d[3])
        : "r"(a0), "r"(a1), "r"(a2), "r"(a3), "r"(b0), "r"(b1));
}

// split 2 floats into hi/lo packed half2 bit patterns (x -> low 16 bits)
__device__ __forceinline__ void split2(float x, float y, uint32_t& hi, uint32_t& lo) {
    __half hx = __float2half_rn(x), hy = __float2half_rn(y);
    __half lx = __float2half_rn(x - __half2float(hx));
    __half ly = __float2half_rn(y - __half2float(hy));
    hi = (uint32_t)__half_as_ushort(hx) | ((uint32_t)__half_as_ushort(hy) << 16);
    lo = (uint32_t)__half_as_ushort(lx) | ((uint32_t)__half_as_ushort(ly) << 16);
}

// ---------------------------------------------------------------------------
// Grid barrier: release/acquire at gpu scope (no MEMBAR.GPU, no L1D flush).
// ---------------------------------------------------------------------------
__device__ __forceinline__ void grid_sync(unsigned* s_sense) {
    __syncthreads();
    if (threadIdx.x == 0) {
        unsigned my = *s_sense ^ 1u;
        *s_sense = my;
        unsigned old;
        asm volatile("atom.release.gpu.global.add.u32 %0, [%1], %2;"
                     : "=r"(old) : "l"(&g_cnt), "r"(1u) : "memory");
        if (old == NCTA - 1u) {
            asm volatile("st.relaxed.gpu.global.u32 [%0], %1;" :: "l"(&g_cnt), "r"(0u) : "memory");
            asm volatile("st.release.gpu.global.u32 [%0], %1;" :: "l"(&g_sense), "r"(my) : "memory");
        } else {
            unsigned cur;
            do {
                asm volatile("ld.acquire.gpu.global.u32 %0, [%1];"
                             : "=r"(cur) : "l"(&g_sense) : "memory");
            } while (cur != my);
        }
    }
    __syncthreads();
}

// ---------------------------------------------------------------------------
// One BM x BN output tile:  C[m,n] = epilogue( sum_k A[m,k]*W[n,k] + bias[n] )
// 3-term fp16 split (AhBh + AhBl + AlBh) — same 2^-22 error structure as the
// tf32 3-term split (both have 10 explicit mantissa bits), half the mmas.
// 256 threads = 8 warps (2x4), warp tile (BM/2)x(BN/4). Double-buffered smem;
// A split on the fly; B streamed via cp.async from pre-split fp16 weights.
// ---------------------------------------------------------------------------
template <int BM, int BN, int MODE>
__device__ __forceinline__ void tile_mma(
    const float* __restrict__ A,
    const __half* __restrict__ Wh, const __half* __restrict__ Wl,
    const float* __restrict__ bias, const float* __restrict__ Zp,
    float* __restrict__ C, int N, int K, float h,
    int mB, int nB, __half2* sm, uint32_t smb) {

    constexpr int MT = BM / 32;        // mma tiles per warp (M): 4 or 2
    constexpr int NT = BN / 32;        // mma tiles per warp (N): 4 or 2
    constexpr int WM = MT * 16;
    constexpr int WN = NT * 8;
    constexpr int AG = BM * 4 / NTHR;  // A 8-float groups per thread
    constexpr int BG = BN * 4 / NTHR;  // B 16B cp groups per thread

    const int tid  = threadIdx.x;
    const int lane = tid & 31;
    const int warp = tid >> 5;
    const int wmi  = warp >> 2;        // 0..1
    const int wni  = warp & 3;         // 0..3
    const int nTc  = K >> 5;

    float4 ra[AG][2];
    float acc[MT][NT][4];
#pragma unroll
    for (int i = 0; i < MT; i++)
#pragma unroll
        for (int j = 0; j < NT; j++)
#pragma unroll
            for (int c = 0; c < 4; c++) acc[i][j][c] = 0.0f;

    auto ldgA = [&](int t) {
#pragma unroll
        for (int i = 0; i < AG; i++) {
            int idx = tid + i * NTHR, row = idx >> 2, g = idx & 3;
            const float* p = A + (size_t)(mB + row) * K + t * 32 + g * 8;
            ra[i][0] = __ldcg((const float4*)p);
            ra[i][1] = __ldcg((const float4*)(p + 4));
        }
    };
    auto cpB = [&](int t, int b) {
        const uint32_t base = smb + (uint32_t)b * (BUF_H * 4) + 2 * TILE_B;
#pragma unroll
        for (int i = 0; i < BG; i++) {
            int idx = tid + i * NTHR, row = idx >> 2, c = idx & 3;
            const size_t o = (size_t)(nB + row) * K + t * 32 + c * 8;
            const uint32_t d = base + (uint32_t)(row * SA + c * 4) * 4;
            cp16(d, Wh + o);
            cp16(d + TILE_B, Wl + o);
        }
        CP_COMMIT();
    };
    auto stsA = [&](int b) {
        __half2* sAh = sm + b * BUF_H;
        __half2* sAl = sAh + TILE_H;
#pragma unroll
        for (int i = 0; i < AG; i++) {
            int idx = tid + i * NTHR, row = idx >> 2, g = idx & 3;
            uint4 hi, lo;
            split2(ra[i][0].x, ra[i][0].y, hi.x, lo.x);
            split2(ra[i][0].z, ra[i][0].w, hi.y, lo.y);
            split2(ra[i][1].x, ra[i][1].y, hi.z, lo.z);
            split2(ra[i][1].z, ra[i][1].w, hi.w, lo.w);
            const int p = row * SA + g * 4;
            *(uint4*)(sAh + p) = hi;
            *(uint4*)(sAl + p) = lo;
        }
    };

    // prologue: fill buffer 0
    ldgA(0);
    cpB(0, 0);
    stsA(0);
    CP_WAIT0();
    __syncthreads();

    const int rA = wmi * WM + (lane >> 2);
    const int rB = wni * WN + (lane >> 2);
    const int cK = lane & 3;           // half2 index within 8-half2 k16 block

    for (int t = 0; t < nTc; ++t) {
        const int cur = t & 1, nxt = cur ^ 1;
        if (t + 1 < nTc) {
            ldgA(t + 1);
            cpB(t + 1, nxt);
        }

        const uint32_t* sAh = (const uint32_t*)(sm + cur * BUF_H);
        const uint32_t* sAl = sAh + TILE_H;
        const uint32_t* sBh = sAl + TILE_H;
        const uint32_t* sBl = sBh + TILE_H;

#pragma unroll
        for (int blk = 0; blk < 2; blk++) {          // two k16 blocks per chunk
            const int kb = blk * 8 + cK;
            uint32_t ah[MT][4], al[MT][4], bh[NT][2], bl[NT][2];
#pragma unroll
            for (int i = 0; i < MT; i++) {
                const int r0 = (rA + i * 16) * SA, r1 = r0 + 8 * SA;
                ah[i][0] = sAh[r0 + kb];
                ah[i][1] = sAh[r1 + kb];
                ah[i][2] = sAh[r0 + kb + 4];
                ah[i][3] = sAh[r1 + kb + 4];
                al[i][0] = sAl[r0 + kb];
                al[i][1] = sAl[r1 + kb];
                al[i][2] = sAl[r0 + kb + 4];
                al[i][3] = sAl[r1 + kb + 4];
            }
#pragma unroll
            for (int j = 0; j < NT; j++) {
                const int rn = (rB + j * 8) * SA;
                bh[j][0] = sBh[rn + kb];
                bh[j][1] = sBh[rn + kb + 4];
                bl[j][0] = sBl[rn + kb];
                bl[j][1] = sBl[rn + kb + 4];
            }
#pragma unroll
            for (int i = 0; i < MT; i++)
#pragma unroll
                for (int j = 0; j < NT; j++) {
                    mma16(acc[i][j], ah[i][0], ah[i][1], ah[i][2], ah[i][3], bh[j][0], bh[j][1]);
                    mma16(acc[i][j], ah[i][0], ah[i][1], ah[i][2], ah[i][3], bl[j][0], bl[j][1]);
                    mma16(acc[i][j], al[i][0], al[i][1], al[i][2], al[i][3], bh[j][0], bh[j][1]);
                }
        }

        if (t + 1 < nTc) {
            stsA(nxt);
            CP_WAIT0();
            __syncthreads();
        }
    }

    // ---- epilogue: bias + mode, float2 stores straight from accumulators ----
#pragma unroll
    for (int i = 0; i < MT; i++) {
        const int gm0 = mB + wmi * WM + i * 16 + (lane >> 2);
#pragma unroll
        for (int j = 0; j < NT; j++) {
            const int gn = nB + wni * WN + j * 8 + (lane & 3) * 2;
            const float bi0 = __ldg(bias + gn), bi1 = __ldg(bias + gn + 1);
            float x0 = acc[i][j][0] + bi0, x1 = acc[i][j][1] + bi1;
            float x2 = acc[i][j][2] + bi0, x3 = acc[i][j][3] + bi1;
            if (MODE == MODE_ELU) {
                x0 = x0 > 0.0f ? x0 : expm1f(x0);
                x1 = x1 > 0.0f ? x1 : expm1f(x1);
                x2 = x2 > 0.0f ? x2 : expm1f(x2);
                x3 = x3 > 0.0f ? x3 : expm1f(x3);
            }
            const size_t g0 = (size_t)gm0 * N + gn;
            const size_t g1 = (size_t)(gm0 + 8) * N + gn;
            if (MODE == MODE_EULER) {
                float2 z0v = __ldcg((const float2*)(Zp + g0));
                float2 z1v = __ldcg((const float2*)(Zp + g1));
                x0 = z0v.x + h * x0; x1 = z0v.y + h * x1;
                x2 = z1v.x + h * x2; x3 = z1v.y + h * x3;
            }
            *(float2*)(C + g0) = make_float2(x0, x1);
            *(float2*)(C + g1) = make_float2(x2, x3);
        }
    }
}

// ---------------------------------------------------------------------------
// Persistent ODE integrator (grid = exactly NCTA x 256 threads).
// Barriers per launch: 1 + 99*10*3 + 1 = 2972 (even -> g_sense ends at 0).
// ---------------------------------------------------------------------------
__global__ void __launch_bounds__(NTHR, 1)
ode_persistent(const float* __restrict__ z0, const float* __restrict__ tv,
               const float* __restrict__ b1, const float* __restrict__ b2,
               const float* __restrict__ b3,
               float* __restrict__ zs, float* __restrict__ h1,
               float* __restrict__ h2, float* __restrict__ za,
               float* __restrict__ zb) {
    extern __shared__ __half2 sm[];
    const uint32_t smb = smem_u32(sm);
    __shared__ unsigned s_sense;
    if (threadIdx.x == 0) s_sense = 0u;

    // zs[0] = z0
    for (int i = blockIdx.x * NTHR + threadIdx.x; i < BATCH * LAT / 4; i += NCTA * NTHR)
        ((float4*)zs)[i] = __ldcg(((const float4*)z0) + i);
    grid_sync(&s_sense);                                    // barrier 1

    const int bx  = blockIdx.x;
    const int mB1 = (bx >> 3) * 128, nB1 = (bx & 7) * 128;  // 16x8 tiles of 128x128
    const int mB3 = (bx >> 2) * 64,  nB3 = (bx & 3) * 64;   // 32x4 tiles of 64x64
    const size_t BL = (size_t)BATCH * LAT;

    for (int it = 0; it < TSTEPS - 1; ++it) {
        const float hstep = (__ldg(tv + it + 1) - __ldg(tv + it)) * (1.0f / NSUB);
        for (int s = 0; s < NSUB; s++) {
            const float* zin  = (s == 0)        ? zs + (size_t)it * BL
                                                : ((s & 1) ? za : zb);
            float*       zout = (s == NSUB - 1) ? zs + (size_t)(it + 1) * BL
                                                : ((s & 1) ? zb : za);
            // h1 = elu(z @ w1.T + b1)   [2048x1024, K=256]
            tile_mma<128, 128, MODE_ELU>(zin, g_w1h, g_w1l, b1, nullptr, h1,
                                         HID, LAT, 0.f, mB1, nB1, sm, smb);
            grid_sync(&s_sense);
            // h2 = elu(h1 @ w2.T + b2)  [2048x1024, K=1024]
            tile_mma<128, 128, MODE_ELU>(h1, g_w2h, g_w2l, b2, nullptr, h2,
                                         HID, HID, 0.f, mB1, nB1, sm, smb);
            grid_sync(&s_sense);
            // zout = zin + h*(h2 @ w3.T + b3)  [2048x256, K=1024]
            tile_mma<64, 64, MODE_EULER>(h2, g_w3h, g_w3l, b3, zin, zout,
                                         LAT, HID, hstep, mB3, nB3, sm, smb);
            grid_sync(&s_sense);
        }
    }
    grid_sync(&s_sense);   // pad -> even count (2972)
}

// ---------------------------------------------------------------------------
// Folded decoder: out = zs @ Md.T + cd   (M=204800, N=512, K=256)
// ---------------------------------------------------------------------------
__global__ void __launch_bounds__(NTHR, 1)
decoder_gemm(const float* __restrict__ zs, const float* __restrict__ cd,
             float* __restrict__ out) {
    extern __shared__ __half2 sm[];
    const uint32_t smb = smem_u32(sm);
    tile_mma<128, 128, MODE_PLAIN>(zs, g_Mdh, g_Mdl, cd, nullptr, out,
                                   OUTD, LAT, 0.f,
                                   blockIdx.y * 128, blockIdx.x * 128, sm, smb);
}

// ---------------------------------------------------------------------------
// Prep: decoder fold + fp16 hi/lo weight splits (tiny, once per launch)
// ---------------------------------------------------------------------------
__global__ void combine_kernel(const float* __restrict__ h2o_w,
                               const float* __restrict__ l2h_w,
                               float* __restrict__ Md) {
    __shared__ float sW[16][17];
    __shared__ float sL[16][17];
    const int o = blockIdx.y * 16 + threadIdx.y;
    const int l = blockIdx.x * 16 + threadIdx.x;
    float acc = 0.0f;
    for (int h0 = 0; h0 < HID; h0 += 16) {
        sW[threadIdx.y][threadIdx.x] = h2o_w[(size_t)o * HID + h0 + threadIdx.x];
        sL[threadIdx.y][threadIdx.x] = l2h_w[(size_t)(h0 + threadIdx.y) * LAT + l];
        __syncthreads();
#pragma unroll
        for (int kk = 0; kk < 16; kk++) acc += sW[threadIdx.y][kk] * sL[kk][threadIdx.x];
        __syncthreads();
    }
    Md[(size_t)o * LAT + l] = acc;
}

__global__ void cvec_kernel(const float* __restrict__ h2o_w,
                            const float* __restrict__ l2h_b,
                            const float* __restrict__ h2o_b,
                            float* __restrict__ cd) {
    const int o = blockIdx.x * blockDim.x + threadIdx.x;
    if (o < OUTD) {
        float a = h2o_b[o];
        for (int h = 0; h < HID; h++) a += h2o_w[(size_t)o * HID + h] * l2h_b[h];
        cd[o] = a;
    }
}

__global__ void split_kernel(const float* __restrict__ w,
                             __half* __restrict__ wh, __half* __restrict__ wl, int n) {
    const int i = blockIdx.x * blockDim.x + threadIdx.x;
    if (i < n) {
        float x = w[i];
        __half hi = __float2half_rn(x);
        wh[i] = hi;
        wl[i] = __float2half_rn(x - __half2float(hi));
    }
}

// ---------------------------------------------------------------------------
// Graph nodes: combine, cvec, 4x split, persistent ODE, decoder.
// ---------------------------------------------------------------------------
extern "C" void kernel_launch(void* const* d_in, const int* in_sizes, int n_in,
                              void* d_out, int out_size) {
    const float* z0    = (const float*)d_in[0];
    const float* tv    = (const float*)d_in[1];
    const float* w1    = (const float*)d_in[2];
    const float* b1    = (const float*)d_in[3];
    const float* w2    = (const float*)d_in[4];
    const float* b2    = (const float*)d_in[5];
    const float* w3    = (const float*)d_in[6];
    const float* b3    = (const float*)d_in[7];
    const float* l2h_w = (const float*)d_in[8];
    const float* l2h_b = (const float*)d_in[9];
    const float* h2o_w = (const float*)d_in[10];
    const float* h2o_b = (const float*)d_in[11];
    float* out = (float*)d_out;

    float *zs, *h1, *h2, *za, *zb, *Md, *cd;
    __half *w1h, *w1l, *w2h, *w2l, *w3h, *w3l, *Mdh, *Mdl;
    cudaGetSymbolAddress((void**)&zs, g_zs);
    cudaGetSymbolAddress((void**)&h1, g_h1);
    cudaGetSymbolAddress((void**)&h2, g_h2);
    cudaGetSymbolAddress((void**)&za, g_za);
    cudaGetSymbolAddress((void**)&zb, g_zb);
    cudaGetSymbolAddress((void**)&Md, g_Md);
    cudaGetSymbolAddress((void**)&cd, g_cd);
    cudaGetSymbolAddress((void**)&w1h, g_w1h);
    cudaGetSymbolAddress((void**)&w1l, g_w1l);
    cudaGetSymbolAddress((void**)&w2h, g_w2h);
    cudaGetSymbolAddress((void**)&w2l, g_w2l);
    cudaGetSymbolAddress((void**)&w3h, g_w3h);
    cudaGetSymbolAddress((void**)&w3l, g_w3l);
    cudaGetSymbolAddress((void**)&Mdh, g_Mdh);
    cudaGetSymbolAddress((void**)&Mdl, g_Mdl);

    static bool attr_done = false;
    if (!attr_done) {
        cudaFuncSetAttribute(ode_persistent,
                             cudaFuncAttributeMaxDynamicSharedMemorySize, SMEM_BYTES);
        cudaFuncSetAttribute(decoder_gemm,
                             cudaFuncAttributeMaxDynamicSharedMemorySize, SMEM_BYTES);
        attr_done = true;
    }

    // prep: decoder fold + weight splits
    combine_kernel<<<dim3(LAT / 16, OUTD / 16), dim3(16, 16)>>>(h2o_w, l2h_w, Md);
    cvec_kernel<<<2, 256>>>(h2o_w, l2h_b, h2o_b, cd);
    split_kernel<<<(HID * LAT + 255) / 256, 256>>>(w1, w1h, w1l, HID * LAT);
    split_kernel<<<(HID * HID + 255) / 256, 256>>>(w2, w2h, w2l, HID * HID);
    split_kernel<<<(LAT * HID + 255) / 256, 256>>>(w3, w3h, w3l, LAT * HID);
    split_kernel<<<(OUTD * LAT + 255) / 256, 256>>>(Md, Mdh, Mdl, OUTD * LAT);

    ode_persistent<<<NCTA, NTHR, SMEM_BYTES>>>(z0, tv, b1, b2, b3,
                                               zs, h1, h2, za, zb);

    decoder_gemm<<<dim3(OUTD / 128, TSTEPS * BATCH / 128), NTHR, SMEM_BYTES>>>(zs, cd, out);
}